// round 1
// baseline (speedup 1.0000x reference)
#include <cuda_runtime.h>

// ---------------------------------------------------------------------------
// Sparse 3D CNN (submanifold conv + masked maxpool pyramid), fp32.
// Grid 64^3 -> 1^3, channels 3 -> 256.
// Level 0 convs: compacted active-voxel gather kernels (occ ~36.7%).
// Levels >=1: dense smem-row-tiled conv with mask multiply (occ ~97-100%).
// ---------------------------------------------------------------------------

#define VOL0 (64 * 64 * 64)
#define MAXE (64 * 64 * 64 * 64)

__device__ float g_bufA[MAXE];
__device__ float g_bufB[MAXE];
__device__ float g_maskA[VOL0];
__device__ float g_maskB[VOL0];
__device__ int   g_owner[VOL0];
__device__ int   g_list[VOL0];
__device__ int   g_cnt;

// ---------------------------------------------------------------------------
__global__ void k_reset(int* __restrict__ owner) {
    int i = blockIdx.x * blockDim.x + threadIdx.x;
    if (i == 0) g_cnt = 0;
    if (i < VOL0) owner[i] = -1;
}

__global__ void k_scatter(const int* __restrict__ coors, int n, int* __restrict__ owner) {
    int i = blockIdx.x * blockDim.x + threadIdx.x;
    if (i >= n) return;
    int z = coors[3 * i], y = coors[3 * i + 1], x = coors[3 * i + 2];
    atomicMax(&owner[(z * 64 + y) * 64 + x], i);  // last-write-wins (max point idx)
}

__global__ void k_build(const int* __restrict__ owner, const float* __restrict__ feat,
                        float* __restrict__ A, float* __restrict__ mask) {
    int v = blockIdx.x * blockDim.x + threadIdx.x;
    if (v >= VOL0) return;
    int o = owner[v];
    if (o >= 0) {
        mask[v] = 1.0f;
        A[3 * v + 0] = feat[3 * o + 0];
        A[3 * v + 1] = feat[3 * o + 1];
        A[3 * v + 2] = feat[3 * o + 2];
        int p = atomicAdd(&g_cnt, 1);
        g_list[p] = v;
    } else {
        mask[v] = 0.0f;
        A[3 * v + 0] = 0.0f;
        A[3 * v + 1] = 0.0f;
        A[3 * v + 2] = 0.0f;
    }
}

__global__ void k_fill0(float4* __restrict__ p, int n4) {
    int i = blockIdx.x * blockDim.x + threadIdx.x;
    if (i < n4) p[i] = make_float4(0.f, 0.f, 0.f, 0.f);
}

// ---------------------------------------------------------------------------
// Sparse conv at level 0 (D=64), COUT=64. Block: 128 thr = 32 cout-lanes x 4
// voxel-groups; each thread handles 8 active voxels x 2 couts.
// ---------------------------------------------------------------------------
template <int CIN>
__global__ void __launch_bounds__(128) k_conv_sparse(
    const float* __restrict__ in, float* __restrict__ out,
    const float* __restrict__ W) {
    const int lane = threadIdx.x & 31;
    const int vg = threadIdx.x >> 5;
    const int VT = 8;
    const int cnt = g_cnt;
    const int base = blockIdx.x * 32 + vg * VT;
    if (blockIdx.x * 32 >= cnt) return;

    int vids[VT], zs[VT], ys[VT], xs[VT];
#pragma unroll
    for (int i = 0; i < VT; i++) {
        int p = base + i;
        int v = (p < cnt) ? g_list[p] : -1;
        vids[i] = v;
        zs[i] = v >> 12;
        ys[i] = (v >> 6) & 63;
        xs[i] = v & 63;
    }

    float acc[VT][2];
#pragma unroll
    for (int i = 0; i < VT; i++) { acc[i][0] = 0.f; acc[i][1] = 0.f; }

#pragma unroll 1
    for (int tap = 0; tap < 27; ++tap) {
        const int dz = tap / 9 - 1;
        const int dy = (tap / 3) % 3 - 1;
        const int dx = tap % 3 - 1;
        const float* wp = W + tap * CIN * 64 + lane;

        int  offs[VT];
        bool val[VT];
#pragma unroll
        for (int i = 0; i < VT; i++) {
            int zz = zs[i] + dz, yy = ys[i] + dy, xx = xs[i] + dx;
            val[i] = (vids[i] >= 0) & (zz >= 0) & (zz < 64) & (yy >= 0) & (yy < 64) &
                     (xx >= 0) & (xx < 64);
            offs[i] = (((zz * 64 + yy) * 64 + xx)) * CIN;
        }

        if (CIN == 3) {
#pragma unroll
            for (int ci = 0; ci < 3; ci++) {
                float w0 = wp[ci * 64];
                float w1 = wp[ci * 64 + 32];
#pragma unroll
                for (int i = 0; i < VT; i++) {
                    float a = val[i] ? in[offs[i] + ci] : 0.f;
                    acc[i][0] = fmaf(a, w0, acc[i][0]);
                    acc[i][1] = fmaf(a, w1, acc[i][1]);
                }
            }
        } else {
#pragma unroll 1
            for (int cig = 0; cig < CIN; cig += 4) {
                float w0[4], w1[4];
#pragma unroll
                for (int q = 0; q < 4; q++) {
                    w0[q] = wp[(cig + q) * 64];
                    w1[q] = wp[(cig + q) * 64 + 32];
                }
#pragma unroll
                for (int i = 0; i < VT; i++) {
                    float4 a = val[i]
                        ? *reinterpret_cast<const float4*>(in + offs[i] + cig)
                        : make_float4(0.f, 0.f, 0.f, 0.f);
                    acc[i][0] = fmaf(a.x, w0[0], acc[i][0]);
                    acc[i][1] = fmaf(a.x, w1[0], acc[i][1]);
                    acc[i][0] = fmaf(a.y, w0[1], acc[i][0]);
                    acc[i][1] = fmaf(a.y, w1[1], acc[i][1]);
                    acc[i][0] = fmaf(a.z, w0[2], acc[i][0]);
                    acc[i][1] = fmaf(a.z, w1[2], acc[i][1]);
                    acc[i][0] = fmaf(a.w, w0[3], acc[i][0]);
                    acc[i][1] = fmaf(a.w, w1[3], acc[i][1]);
                }
            }
        }
    }

#pragma unroll
    for (int i = 0; i < VT; i++) {
        if (vids[i] >= 0) {
            int o = vids[i] * 64 + lane;
            out[o] = acc[i][0];
            out[o + 32] = acc[i][1];
        }
    }
}

// ---------------------------------------------------------------------------
// Dense conv (levels >= 1). Block: 128 thr = 32 cout-lanes x 4 x-groups.
// Tile: XT consecutive x at fixed (z,y). smem holds 3x3 rows with x halo.
// ---------------------------------------------------------------------------
template <int CIN, int COUT, int XT>
__global__ void __launch_bounds__(128) k_conv_dense(
    const float* __restrict__ in, float* __restrict__ out,
    const float* __restrict__ W, const float* __restrict__ mask, int D) {
    constexpr int XPAD = XT + 2;
    constexpr int COT = COUT / 32;
    constexpr int XTT = (XT + 3) / 4;

    __shared__ __align__(16) float sm[9][XPAD][CIN];

    const int lane = threadIdx.x & 31;
    const int xg = threadIdx.x >> 5;
    const int z = blockIdx.z, y = blockIdx.y;
    const int x0 = blockIdx.x * XT;

    bool rowok[9];
#pragma unroll 1
    for (int r = 0; r < 9; r++) {
        int dz = r / 3 - 1, dy = r % 3 - 1;
        int zz = z + dz, yy = y + dy;
        bool ok = (zz >= 0) & (zz < D) & (yy >= 0) & (yy < D);
        rowok[r] = ok;
        const float* rp = in + ((long)(zz * D + yy) * D) * CIN;
        for (int idx = threadIdx.x; idx < XPAD * CIN; idx += 128) {
            int xi = idx / CIN;
            int ci = idx - xi * CIN;
            int gx = x0 - 1 + xi;
            float v = 0.f;
            if (ok && gx >= 0 && gx < D) v = rp[gx * CIN + ci];
            sm[r][xi][ci] = v;
        }
    }
    __syncthreads();

    const bool active_x = (xg * XTT) < XT;

    float acc[XTT][COT];
#pragma unroll
    for (int i = 0; i < XTT; i++)
#pragma unroll
        for (int j = 0; j < COT; j++) acc[i][j] = 0.f;

    if (active_x) {
#pragma unroll 1
        for (int r = 0; r < 9; r++) {
            if (!rowok[r]) continue;
#pragma unroll 1
            for (int dx = 0; dx < 3; dx++) {
                const float* wp = W + (r * 3 + dx) * CIN * COUT + lane;
#pragma unroll 2
                for (int cig = 0; cig < CIN; cig += 4) {
                    float w[4][COT];
#pragma unroll
                    for (int q = 0; q < 4; q++)
#pragma unroll
                        for (int j = 0; j < COT; j++)
                            w[q][j] = wp[(cig + q) * COUT + j * 32];
#pragma unroll
                    for (int i = 0; i < XTT; i++) {
                        int xi = xg * XTT + i + dx;
                        float4 a = *reinterpret_cast<const float4*>(&sm[r][xi][cig]);
#pragma unroll
                        for (int j = 0; j < COT; j++) {
                            acc[i][j] = fmaf(a.x, w[0][j], acc[i][j]);
                            acc[i][j] = fmaf(a.y, w[1][j], acc[i][j]);
                            acc[i][j] = fmaf(a.z, w[2][j], acc[i][j]);
                            acc[i][j] = fmaf(a.w, w[3][j], acc[i][j]);
                        }
                    }
                }
            }
        }
    }

#pragma unroll
    for (int i = 0; i < XTT; i++) {
        int xl = xg * XTT + i;
        if (xl >= XT) continue;
        int gx = x0 + xl;
        float m = mask[(z * D + y) * D + gx];
        int o = ((z * D + y) * D + gx) * COUT + lane;
#pragma unroll
        for (int j = 0; j < COT; j++) out[o + j * 32] = acc[i][j] * m;
    }
}

// ---------------------------------------------------------------------------
// Masked 2x2x2 max pool: in (Di=2*Do)^3 x C -> out Do^3 x C, mask likewise.
// ---------------------------------------------------------------------------
__global__ void k_pool(const float* __restrict__ in, const float* __restrict__ im,
                       float* __restrict__ out, float* __restrict__ om,
                       int Do, int C) {
    int idx = blockIdx.x * blockDim.x + threadIdx.x;
    int total = Do * Do * Do * C;
    if (idx >= total) return;
    int c = idx % C;
    int v = idx / C;
    int xo = v % Do;
    int yo = (v / Do) % Do;
    int zo = v / (Do * Do);
    int Di = Do * 2;
    float best = -3.4e38f;
    bool any = false;
#pragma unroll
    for (int a = 0; a < 2; a++)
#pragma unroll
        for (int b = 0; b < 2; b++)
#pragma unroll
            for (int d = 0; d < 2; d++) {
                int vi = ((2 * zo + a) * Di + (2 * yo + b)) * Di + (2 * xo + d);
                if (im[vi] > 0.f) {
                    any = true;
                    float t = in[vi * C + c];
                    best = t > best ? t : best;
                }
            }
    out[v * C + c] = any ? best : 0.f;
    if (c == 0) om[v] = any ? 1.f : 0.f;
}

__global__ void k_copy(const float* __restrict__ in, float* __restrict__ out, int n) {
    int i = blockIdx.x * blockDim.x + threadIdx.x;
    if (i < n) out[i] = in[i];
}

// ---------------------------------------------------------------------------
static void launch_dense(int wi, const float* in, float* out, const float* W,
                         const float* mask, int D) {
    switch (wi) {
        case 2:  k_conv_dense< 64,  96, 16><<<dim3(D / 16, D, D), 128>>>(in, out, W, mask, D); break;
        case 3:  k_conv_dense< 96,  96,  8><<<dim3(D /  8, D, D), 128>>>(in, out, W, mask, D); break;
        case 4:  k_conv_dense< 96, 128,  8><<<dim3(D /  8, D, D), 128>>>(in, out, W, mask, D); break;
        case 5:  k_conv_dense<128, 128,  8><<<dim3(D /  8, D, D), 128>>>(in, out, W, mask, D); break;
        case 6:  k_conv_dense<128, 160,  8><<<dim3(D /  8, D, D), 128>>>(in, out, W, mask, D); break;
        case 7:  k_conv_dense<160, 160,  4><<<dim3(D /  4, D, D), 128>>>(in, out, W, mask, D); break;
        case 8:  k_conv_dense<160, 192,  4><<<dim3(D /  4, D, D), 128>>>(in, out, W, mask, D); break;
        case 9:  k_conv_dense<192, 192,  4><<<dim3(D /  4, D, D), 128>>>(in, out, W, mask, D); break;
        case 10: k_conv_dense<192, 224,  2><<<dim3(D /  2, D, D), 128>>>(in, out, W, mask, D); break;
        case 11: k_conv_dense<224, 224,  2><<<dim3(D /  2, D, D), 128>>>(in, out, W, mask, D); break;
        case 12: k_conv_dense<224, 256,  1><<<dim3(D /  1, D, D), 128>>>(in, out, W, mask, D); break;
        case 13: k_conv_dense<256, 256,  1><<<dim3(D /  1, D, D), 128>>>(in, out, W, mask, D); break;
    }
}

extern "C" void kernel_launch(void* const* d_in, const int* in_sizes, int n_in,
                              void* d_out, int out_size) {
    const float* feat = (const float*)d_in[0];
    const int* coors = (const int*)d_in[1];
    const float* W[14];
    for (int i = 0; i < 14; i++) W[i] = (const float*)d_in[2 + i];

    float *A, *B, *MA, *MB;
    int* OWN;
    cudaGetSymbolAddress((void**)&A, g_bufA);
    cudaGetSymbolAddress((void**)&B, g_bufB);
    cudaGetSymbolAddress((void**)&MA, g_maskA);
    cudaGetSymbolAddress((void**)&MB, g_maskB);
    cudaGetSymbolAddress((void**)&OWN, g_owner);

    const int N = in_sizes[0] / 3;

    k_reset<<<(VOL0 + 255) / 256, 256>>>(OWN);
    k_scatter<<<(N + 255) / 256, 256>>>(coors, N, OWN);
    k_build<<<(VOL0 + 255) / 256, 256>>>(OWN, feat, A, MA);

    float* cur = A;
    float* alt = B;
    float* mcur = MA;
    float* malt = MB;
    float* t;

    // ----- Block 0 (D=64): sparse convs -----
    const int n4 = VOL0 * 64 / 4;
    const int sparse_blocks = (120000 + 31) / 32;

    k_fill0<<<(n4 + 255) / 256, 256>>>((float4*)alt, n4);
    k_conv_sparse<3><<<sparse_blocks, 128>>>(cur, alt, W[0]);
    t = cur; cur = alt; alt = t;

    k_fill0<<<(n4 + 255) / 256, 256>>>((float4*)alt, n4);
    k_conv_sparse<64><<<sparse_blocks, 128>>>(cur, alt, W[1]);
    t = cur; cur = alt; alt = t;

    {
        int Do = 32, C = 64;
        k_pool<<<(Do * Do * Do * C + 255) / 256, 256>>>(cur, mcur, alt, malt, Do, C);
        t = cur; cur = alt; alt = t;
        t = mcur; mcur = malt; malt = t;
    }

    // ----- Blocks 1..6: dense -----
    const int Ds[7]   = {64, 32, 16, 8, 4, 2, 1};
    const int couts[14] = {64, 64, 96, 96, 128, 128, 160, 160, 192, 192, 224, 224, 256, 256};
    int wi = 2;
    for (int b = 1; b < 7; b++) {
        int D = Ds[b];
        launch_dense(wi, cur, alt, W[wi], mcur, D);
        t = cur; cur = alt; alt = t;
        wi++;
        launch_dense(wi, cur, alt, W[wi], mcur, D);
        t = cur; cur = alt; alt = t;
        wi++;
        if (b < 6) {
            int Do = D / 2;
            int C = couts[wi - 1];
            k_pool<<<(Do * Do * Do * C + 255) / 256, 256>>>(cur, mcur, alt, malt, Do, C);
            t = cur; cur = alt; alt = t;
            t = mcur; mcur = malt; malt = t;
        }
    }

    k_copy<<<(out_size + 255) / 256, 256>>>(cur, (float*)d_out, out_size);
}

// round 3
// speedup vs baseline: 1.0618x; 1.0618x over previous
#include <cuda_runtime.h>

// ---------------------------------------------------------------------------
// Sparse 3D CNN (submanifold conv + masked maxpool pyramid), fp32.
// 64^3 -> 1^3, channels 3 -> 256. All convs smem-free: data loads are
// warp-uniform broadcasts (lane indexes cout), weights coalesced per-lane.
// ---------------------------------------------------------------------------

#define VOL0 (64 * 64 * 64)
#define MAXE (64 * 64 * 64 * 64)

__device__ float g_bufA[MAXE];
__device__ float g_bufB[MAXE];
__device__ float g_maskA[VOL0];
__device__ float g_maskB[VOL0];
__device__ int   g_owner[VOL0];
__device__ int   g_list[VOL0];
__device__ int   g_cnt;

// ---------------------------------------------------------------------------
__global__ void k_reset(int* __restrict__ owner) {
    int i = blockIdx.x * blockDim.x + threadIdx.x;
    if (i == 0) g_cnt = 0;
    if (i < VOL0) owner[i] = -1;
}

__global__ void k_scatter(const int* __restrict__ coors, int n, int* __restrict__ owner) {
    int i = blockIdx.x * blockDim.x + threadIdx.x;
    if (i >= n) return;
    int z = coors[3 * i], y = coors[3 * i + 1], x = coors[3 * i + 2];
    atomicMax(&owner[(z * 64 + y) * 64 + x], i);  // last-write-wins
}

__global__ void k_build(const int* __restrict__ owner, const float* __restrict__ feat,
                        float* __restrict__ A, float* __restrict__ mask) {
    int v = blockIdx.x * blockDim.x + threadIdx.x;
    if (v >= VOL0) return;
    int o = owner[v];
    if (o >= 0) {
        mask[v] = 1.0f;
        A[3 * v + 0] = feat[3 * o + 0];
        A[3 * v + 1] = feat[3 * o + 1];
        A[3 * v + 2] = feat[3 * o + 2];
        int p = atomicAdd(&g_cnt, 1);
        g_list[p] = v;
    } else {
        mask[v] = 0.0f;
        A[3 * v + 0] = 0.0f;
        A[3 * v + 1] = 0.0f;
        A[3 * v + 2] = 0.0f;
    }
}

__global__ void k_fill0(float4* __restrict__ p, int n4) {
    int i = blockIdx.x * blockDim.x + threadIdx.x;
    if (i < n4) p[i] = make_float4(0.f, 0.f, 0.f, 0.f);
}

// ---------------------------------------------------------------------------
// Sparse conv 3 -> 64 at level 0. 128 thr = 4 warps x (32 lanes = 64 couts
// via float2). Each warp: VT active voxels.
// ---------------------------------------------------------------------------
__global__ void __launch_bounds__(128) k_conv_s0(
    const float* __restrict__ in, float* __restrict__ out,
    const float* __restrict__ W) {
    constexpr int VT = 10;
    const int lane = threadIdx.x & 31;
    const int vg = threadIdx.x >> 5;
    const int cnt = g_cnt;
    const int base = blockIdx.x * (4 * VT) + vg * VT;
    if (blockIdx.x * (4 * VT) >= cnt) return;

    int vids[VT];
#pragma unroll
    for (int i = 0; i < VT; i++) {
        int p = base + i;
        vids[i] = (p < cnt) ? g_list[p] : -1;
    }

    float2 acc[VT];
#pragma unroll
    for (int i = 0; i < VT; i++) { acc[i].x = 0.f; acc[i].y = 0.f; }

#pragma unroll 1
    for (int tap = 0; tap < 27; ++tap) {
        const int dz = tap / 9 - 1;
        const int dy = (tap / 3) % 3 - 1;
        const int dx = tap % 3 - 1;
        const float2* wp = reinterpret_cast<const float2*>(W + tap * 3 * 64) + lane;
        float2 w0 = wp[0], w1 = wp[32], w2 = wp[64];

        int offs[VT];
        bool val[VT];
#pragma unroll
        for (int i = 0; i < VT; i++) {
            int v = vids[i];
            int zz = (v >> 12) + dz, yy = ((v >> 6) & 63) + dy, xx = (v & 63) + dx;
            val[i] = (v >= 0) & ((unsigned)zz < 64u) & ((unsigned)yy < 64u) &
                     ((unsigned)xx < 64u);
            offs[i] = ((zz * 64 + yy) * 64 + xx) * 3;
        }
#pragma unroll
        for (int i = 0; i < VT; i++) {
            float a0 = val[i] ? in[offs[i] + 0] : 0.f;
            float a1 = val[i] ? in[offs[i] + 1] : 0.f;
            float a2 = val[i] ? in[offs[i] + 2] : 0.f;
            acc[i].x = fmaf(a0, w0.x, acc[i].x);
            acc[i].y = fmaf(a0, w0.y, acc[i].y);
            acc[i].x = fmaf(a1, w1.x, acc[i].x);
            acc[i].y = fmaf(a1, w1.y, acc[i].y);
            acc[i].x = fmaf(a2, w2.x, acc[i].x);
            acc[i].y = fmaf(a2, w2.y, acc[i].y);
        }
    }

#pragma unroll
    for (int i = 0; i < VT; i++)
        if (vids[i] >= 0)
            *reinterpret_cast<float2*>(out + vids[i] * 64 + 2 * lane) = acc[i];
}

// ---------------------------------------------------------------------------
// Sparse conv 64 -> 64 at level 0 (the big one, ~10.6 GMAC).
// ---------------------------------------------------------------------------
__global__ void __launch_bounds__(128) k_conv_s64(
    const float* __restrict__ in, float* __restrict__ out,
    const float* __restrict__ W) {
    constexpr int VT = 10;
    const int lane = threadIdx.x & 31;
    const int vg = threadIdx.x >> 5;
    const int cnt = g_cnt;
    const int base = blockIdx.x * (4 * VT) + vg * VT;
    if (blockIdx.x * (4 * VT) >= cnt) return;

    int vids[VT];
#pragma unroll
    for (int i = 0; i < VT; i++) {
        int p = base + i;
        vids[i] = (p < cnt) ? g_list[p] : -1;
    }

    float2 acc[VT];
#pragma unroll
    for (int i = 0; i < VT; i++) { acc[i].x = 0.f; acc[i].y = 0.f; }

#pragma unroll 1
    for (int tap = 0; tap < 27; ++tap) {
        const int dz = tap / 9 - 1;
        const int dy = (tap / 3) % 3 - 1;
        const int dx = tap % 3 - 1;
        const float2* wp = reinterpret_cast<const float2*>(W + tap * 64 * 64) + lane;

        int offs[VT];
        bool val[VT];
#pragma unroll
        for (int i = 0; i < VT; i++) {
            int v = vids[i];
            int zz = (v >> 12) + dz, yy = ((v >> 6) & 63) + dy, xx = (v & 63) + dx;
            val[i] = (v >= 0) & ((unsigned)zz < 64u) & ((unsigned)yy < 64u) &
                     ((unsigned)xx < 64u);
            offs[i] = ((zz * 64 + yy) * 64 + xx) * 64;
        }

#pragma unroll 1
        for (int c = 0; c < 64; c += 4) {
            float2 w0 = wp[(c + 0) * 32];
            float2 w1 = wp[(c + 1) * 32];
            float2 w2 = wp[(c + 2) * 32];
            float2 w3 = wp[(c + 3) * 32];
#pragma unroll
            for (int i = 0; i < VT; i++) {
                float4 a = val[i]
                    ? *reinterpret_cast<const float4*>(in + offs[i] + c)
                    : make_float4(0.f, 0.f, 0.f, 0.f);
                acc[i].x = fmaf(a.x, w0.x, acc[i].x);
                acc[i].y = fmaf(a.x, w0.y, acc[i].y);
                acc[i].x = fmaf(a.y, w1.x, acc[i].x);
                acc[i].y = fmaf(a.y, w1.y, acc[i].y);
                acc[i].x = fmaf(a.z, w2.x, acc[i].x);
                acc[i].y = fmaf(a.z, w2.y, acc[i].y);
                acc[i].x = fmaf(a.w, w3.x, acc[i].x);
                acc[i].y = fmaf(a.w, w3.y, acc[i].y);
            }
        }
    }

#pragma unroll
    for (int i = 0; i < VT; i++)
        if (vids[i] >= 0)
            *reinterpret_cast<float2*>(out + vids[i] * 64 + 2 * lane) = acc[i];
}

// ---------------------------------------------------------------------------
// Dense conv, smem-free. Block = 32*WX*WC threads. Warp -> (wc cout group,
// wx x group). Thread: XTT x-positions, COT couts.
// CONTIG: couts are contiguous per thread (float2 weight/output when COT==2).
// ---------------------------------------------------------------------------
template <int CIN, int COUT, int WX, int WC, int COT, int XTT, bool CONTIG>
__global__ void __launch_bounds__(32 * WX * WC) k_convd(
    const float* __restrict__ in, float* __restrict__ out,
    const float* __restrict__ W, const float* __restrict__ mask, int D) {
    const int lane = threadIdx.x & 31;
    const int wrp = threadIdx.x >> 5;
    const int wc = wrp % WC;
    const int wx = wrp / WC;
    const int z = blockIdx.z, y = blockIdx.y;
    const int x0 = blockIdx.x * (WX * XTT) + wx * XTT;
    const int co0 = CONTIG ? (lane + 32 * wc) * COT : (lane + 32 * wc);

    float acc[XTT][COT];
#pragma unroll
    for (int i = 0; i < XTT; i++)
#pragma unroll
        for (int j = 0; j < COT; j++) acc[i][j] = 0.f;

#pragma unroll 1
    for (int r = 0; r < 9; r++) {
        const int dz = r / 3 - 1, dy = r % 3 - 1;
        const int zz = z + dz, yy = y + dy;
        if ((unsigned)zz >= (unsigned)D || (unsigned)yy >= (unsigned)D) continue;
        const float* rowp = in + (size_t)((zz * D + yy) * D) * CIN;
#pragma unroll 1
        for (int dx = 0; dx < 3; dx++) {
            const float* wp = W + (size_t)((r * 3 + dx) * CIN) * COUT + co0;
            int offs[XTT];
            bool val[XTT];
#pragma unroll
            for (int i = 0; i < XTT; i++) {
                int gx = x0 + i + dx - 1;
                val[i] = (unsigned)gx < (unsigned)D;
                offs[i] = gx * CIN;
            }
#pragma unroll 1
            for (int c = 0; c < CIN; c += 4) {
                float wv[4][COT];
#pragma unroll
                for (int q = 0; q < 4; q++) {
                    if (CONTIG && COT == 2) {
                        float2 t = *reinterpret_cast<const float2*>(wp + (c + q) * COUT);
                        wv[q][0] = t.x;
                        wv[q][1] = t.y;
                    } else {
#pragma unroll
                        for (int j = 0; j < COT; j++)
                            wv[q][j] = wp[(c + q) * COUT + j * 32 * WC];
                    }
                }
#pragma unroll
                for (int i = 0; i < XTT; i++) {
                    float4 a = val[i]
                        ? *reinterpret_cast<const float4*>(rowp + offs[i] + c)
                        : make_float4(0.f, 0.f, 0.f, 0.f);
#pragma unroll
                    for (int j = 0; j < COT; j++) {
                        acc[i][j] = fmaf(a.x, wv[0][j], acc[i][j]);
                        acc[i][j] = fmaf(a.y, wv[1][j], acc[i][j]);
                        acc[i][j] = fmaf(a.z, wv[2][j], acc[i][j]);
                        acc[i][j] = fmaf(a.w, wv[3][j], acc[i][j]);
                    }
                }
            }
        }
    }

    const int vb = (z * D + y) * D;
#pragma unroll
    for (int i = 0; i < XTT; i++) {
        int gx = x0 + i;
        float m = mask[vb + gx];
        float* op = out + (size_t)(vb + gx) * COUT + co0;
        if (CONTIG && COT == 2) {
            float2 t;
            t.x = acc[i][0] * m;
            t.y = acc[i][1] * m;
            *reinterpret_cast<float2*>(op) = t;
        } else {
#pragma unroll
            for (int j = 0; j < COT; j++) op[j * 32 * WC] = acc[i][j] * m;
        }
    }
}

// ---------------------------------------------------------------------------
// Masked 2x2x2 max pool.
// ---------------------------------------------------------------------------
__global__ void k_pool(const float* __restrict__ in, const float* __restrict__ im,
                       float* __restrict__ out, float* __restrict__ om,
                       int Do, int C) {
    int idx = blockIdx.x * blockDim.x + threadIdx.x;
    int total = Do * Do * Do * C;
    if (idx >= total) return;
    int c = idx % C;
    int v = idx / C;
    int xo = v % Do;
    int yo = (v / Do) % Do;
    int zo = v / (Do * Do);
    int Di = Do * 2;
    float best = -3.4e38f;
    bool any = false;
#pragma unroll
    for (int a = 0; a < 2; a++)
#pragma unroll
        for (int b = 0; b < 2; b++)
#pragma unroll
            for (int d = 0; d < 2; d++) {
                int vi = ((2 * zo + a) * Di + (2 * yo + b)) * Di + (2 * xo + d);
                if (im[vi] > 0.f) {
                    any = true;
                    float t = in[vi * C + c];
                    best = t > best ? t : best;
                }
            }
    out[v * C + c] = any ? best : 0.f;
    if (c == 0) om[v] = any ? 1.f : 0.f;
}

// ---------------------------------------------------------------------------
extern "C" void kernel_launch(void* const* d_in, const int* in_sizes, int n_in,
                              void* d_out, int out_size) {
    const float* feat = (const float*)d_in[0];
    const int* coors = (const int*)d_in[1];
    const float* W[14];
    for (int i = 0; i < 14; i++) W[i] = (const float*)d_in[2 + i];

    float *A, *B, *MA, *MB;
    int* OWN;
    cudaGetSymbolAddress((void**)&A, g_bufA);
    cudaGetSymbolAddress((void**)&B, g_bufB);
    cudaGetSymbolAddress((void**)&MA, g_maskA);
    cudaGetSymbolAddress((void**)&MB, g_maskB);
    cudaGetSymbolAddress((void**)&OWN, g_owner);

    const int N = in_sizes[0] / 3;
    const int sb = (N + 39) / 40;  // sparse blocks: 40 voxels each

    k_reset<<<(VOL0 + 255) / 256, 256>>>(OWN);
    k_scatter<<<(N + 255) / 256, 256>>>(coors, N, OWN);
    k_build<<<(VOL0 + 255) / 256, 256>>>(OWN, feat, A, MA);

    // Level 0 (D=64): conv0 output buffer must be zeroed (conv1 gathers it).
    const int n4 = VOL0 * 64 / 4;
    k_fill0<<<(n4 + 255) / 256, 256>>>((float4*)B, n4);
    k_conv_s0<<<sb, 128>>>(A, B, W[0]);
    k_conv_s64<<<sb, 128>>>(B, A, W[1]);  // out only read via masked pool
    k_pool<<<(32 * 32 * 32 * 64 + 255) / 256, 256>>>(A, MA, B, MB, 32, 64);

    // D=32
    k_convd<64, 96, 4, 1, 3, 8, false><<<dim3(1, 32, 32), 128>>>(B, A, W[2], MB, 32);
    k_convd<96, 96, 4, 1, 3, 8, false><<<dim3(1, 32, 32), 128>>>(A, B, W[3], MB, 32);
    k_pool<<<(16 * 16 * 16 * 96 + 255) / 256, 256>>>(B, MB, A, MA, 16, 96);

    // D=16
    k_convd<96, 128, 1, 2, 2, 4, true><<<dim3(4, 16, 16), 64>>>(A, B, W[4], MA, 16);
    k_convd<128, 128, 1, 2, 2, 4, true><<<dim3(4, 16, 16), 64>>>(B, A, W[5], MA, 16);
    k_pool<<<(8 * 8 * 8 * 128 + 255) / 256, 256>>>(A, MA, B, MB, 8, 128);

    // D=8
    k_convd<128, 160, 1, 5, 1, 1, false><<<dim3(8, 8, 8), 160>>>(B, A, W[6], MB, 8);
    k_convd<160, 160, 1, 5, 1, 1, false><<<dim3(8, 8, 8), 160>>>(A, B, W[7], MB, 8);
    k_pool<<<(4 * 4 * 4 * 160 + 255) / 256, 256>>>(B, MB, A, MA, 4, 160);

    // D=4
    k_convd<160, 192, 1, 3, 2, 1, true><<<dim3(4, 4, 4), 96>>>(A, B, W[8], MA, 4);
    k_convd<192, 192, 1, 3, 2, 1, true><<<dim3(4, 4, 4), 96>>>(B, A, W[9], MA, 4);
    k_pool<<<(2 * 2 * 2 * 192 + 255) / 256, 256>>>(A, MA, B, MB, 2, 192);

    // D=2
    k_convd<192, 224, 1, 7, 1, 1, false><<<dim3(2, 2, 2), 224>>>(B, A, W[10], MB, 2);
    k_convd<224, 224, 1, 7, 1, 1, false><<<dim3(2, 2, 2), 224>>>(A, B, W[11], MB, 2);
    k_pool<<<(1 * 224 + 255) / 256, 256>>>(B, MB, A, MA, 1, 224);

    // D=1 -> final output straight into d_out
    k_convd<224, 256, 1, 4, 2, 1, true><<<dim3(1, 1, 1), 128>>>(A, B, W[12], MA, 1);
    k_convd<256, 256, 1, 4, 2, 1, true><<<dim3(1, 1, 1), 128>>>(B, (float*)d_out, W[13], MA, 1);
}